// round 5
// baseline (speedup 1.0000x reference)
#include <cuda_runtime.h>
#include <cuda_bf16.h>
#include <math.h>
#include <stdint.h>

#define NMAX 50000
#define EMAX 200000
#define ETMAX (NMAX + EMAX)

// ---------------- scratch (device globals; no allocations allowed) ----------
__device__ float g_h1[(size_t)NMAX * 1024];
__device__ float g_a1[(size_t)NMAX * 1024];
__device__ float g_h2[(size_t)NMAX * 128];
__device__ float g_a2[(size_t)NMAX * 128];
__device__ float g_h3[(size_t)NMAX * 64];
__device__ float g_a3[(size_t)NMAX * 64];
__device__ float g_es[(size_t)NMAX * 8];
__device__ float g_ed[(size_t)NMAX * 8];
__device__ float g_z [(size_t)NMAX * 8];
__device__ float g_w [(size_t)ETMAX * 8];
__device__ int   g_src[ETMAX];
__device__ int   g_dst[ETMAX];
__device__ int   g_is64;
// transposed + hi/lo-split weights, [Nc][Kpad] bf16 (reused across layers)
__device__ __nv_bfloat16 g_wth[131072];
__device__ __nv_bfloat16 g_wtl[131072];

// ================= edge preprocessing =======================================
__global__ void detect_dtype(const void* ei, int N) {
    if (blockIdx.x == 0 && threadIdx.x == 0) {
        const long long* p = (const long long*)ei;
        int ok = 1;
        for (int i = 0; i < 64; i++) {
            long long v = p[i];
            if (v < 0 || v >= (long long)N) { ok = 0; break; }
        }
        g_is64 = ok;
    }
}
__global__ void prep_edges(const void* ei, int E, int ET) {
    int i = blockIdx.x * blockDim.x + threadIdx.x;
    if (i >= ET) return;
    int s, d;
    if (i < E) {
        if (g_is64) { const long long* p = (const long long*)ei; s = (int)p[i]; d = (int)p[E + i]; }
        else        { const int* p = (const int*)ei; s = p[i]; d = p[E + i]; }
    } else { s = d = i - E; }
    g_src[i] = s; g_dst[i] = d;
}

// transpose + hi/lo split of W[K,N] into Wt[N,Kpad] bf16
__global__ void prep_w(const float* __restrict__ W, __nv_bfloat16* __restrict__ hi,
                       __nv_bfloat16* __restrict__ lo, int K, int N, int Kpad) {
    int idx = blockIdx.x * blockDim.x + threadIdx.x;
    if (idx >= N * Kpad) return;
    int n = idx / Kpad, k = idx - n * Kpad;
    float v = (k < K) ? W[(size_t)k * N + n] : 0.f;
    __nv_bfloat16 h = __float2bfloat16(v);
    hi[idx] = h;
    lo[idx] = __float2bfloat16(v - __bfloat162float(h));
}

// ================= mma.sync bf16-split GEMM ==================================
// C[M, Nc] = A[M, Kg](fp32) @ Wt^T   (Wt stored [Nc, Kpad] bf16 hi/lo)
// CTA tile 128x64, 8 warps of 32x32, K chunk 64. fp32 accum; 3-term split.
#define APAD 72     // smem row stride (elements) for A and B tiles
#define SMEM_GEMM ((9216 * 2 + 4608 * 2) * 2)   // 55296 bytes

__device__ __forceinline__ void mma_bf16(float* c, uint32_t a0, uint32_t a1,
                                         uint32_t a2, uint32_t a3,
                                         uint32_t b0, uint32_t b1) {
    asm volatile(
        "mma.sync.aligned.m16n8k16.row.col.f32.bf16.bf16.f32 "
        "{%0,%1,%2,%3}, {%4,%5,%6,%7}, {%8,%9}, {%0,%1,%2,%3};"
        : "+f"(c[0]), "+f"(c[1]), "+f"(c[2]), "+f"(c[3])
        : "r"(a0), "r"(a1), "r"(a2), "r"(a3), "r"(b0), "r"(b1));
}

__global__ void __launch_bounds__(256, 1)
gemm_mma(const float* __restrict__ A, const __nv_bfloat16* __restrict__ Bh,
         const __nv_bfloat16* __restrict__ Bl, float* __restrict__ C,
         int M, int Kg, int Kpad, int Nc) {
    extern __shared__ __nv_bfloat16 sm[];
    __nv_bfloat16* sAh = sm;                 // [128][APAD]
    __nv_bfloat16* sAl = sAh + 128 * APAD;
    __nv_bfloat16* sBh = sAl + 128 * APAD;   // [64][APAD]
    __nv_bfloat16* sBl = sBh + 64 * APAD;

    const int tid = threadIdx.x;
    const int rowBase = blockIdx.y * 128, colBase = blockIdx.x * 64;
    const int warp = tid >> 5, lane = tid & 31;
    const int wm = warp & 3, wn = warp >> 2;      // 4x2 warp grid
    const int g = lane >> 2, t = lane & 3;
    const bool vecA = ((Kg & 3) == 0);

    float acc[2][4][4] = {};

    for (int k0 = 0; k0 < Kpad; k0 += 64) {
        // ---- A tile: 128 rows x 64 k, fp32 -> bf16 hi/lo ----
        #pragma unroll
        for (int i = 0; i < 8; i++) {
            int lin = tid + (i << 8);
            int row = lin >> 4, q = lin & 15;
            int k = k0 + (q << 2);
            int gr = rowBase + row;
            float4 v = make_float4(0.f, 0.f, 0.f, 0.f);
            if (gr < M) {
                if (vecA && k + 4 <= Kg) {
                    v = *(const float4*)(A + (size_t)gr * Kg + k);
                } else {
                    if (k + 0 < Kg) v.x = A[(size_t)gr * Kg + k + 0];
                    if (k + 1 < Kg) v.y = A[(size_t)gr * Kg + k + 1];
                    if (k + 2 < Kg) v.z = A[(size_t)gr * Kg + k + 2];
                    if (k + 3 < Kg) v.w = A[(size_t)gr * Kg + k + 3];
                }
            }
            __nv_bfloat162 h01, h23, l01, l23;
            h01.x = __float2bfloat16(v.x); h01.y = __float2bfloat16(v.y);
            h23.x = __float2bfloat16(v.z); h23.y = __float2bfloat16(v.w);
            l01.x = __float2bfloat16(v.x - __bfloat162float(h01.x));
            l01.y = __float2bfloat16(v.y - __bfloat162float(h01.y));
            l23.x = __float2bfloat16(v.z - __bfloat162float(h23.x));
            l23.y = __float2bfloat16(v.w - __bfloat162float(h23.y));
            int e = row * APAD + (q << 2);
            *(uint2*)(sAh + e) = make_uint2(*(uint32_t*)&h01, *(uint32_t*)&h23);
            *(uint2*)(sAl + e) = make_uint2(*(uint32_t*)&l01, *(uint32_t*)&l23);
        }
        // ---- B tile: 64 n-rows x 64 k (pre-split bf16) ----
        #pragma unroll
        for (int i = 0; i < 2; i++) {
            int lin = tid + (i << 8);
            int n = lin >> 3, u = lin & 7;
            size_t gidx = (size_t)(colBase + n) * Kpad + k0 + (u << 3);
            int e = n * APAD + (u << 3);
            *(uint4*)(sBh + e) = *(const uint4*)(Bh + gidx);
            *(uint4*)(sBl + e) = *(const uint4*)(Bl + gidx);
        }
        __syncthreads();

        #pragma unroll
        for (int ks = 0; ks < 4; ks++) {
            const int kc = ks * 16 + t * 2;   // element col of this thread's k-pair
            uint32_t ah[2][4], al[2][4];
            #pragma unroll
            for (int ma = 0; ma < 2; ma++) {
                int r0 = wm * 32 + ma * 16 + g;
                ah[ma][0] = *(const uint32_t*)(sAh + r0 * APAD + kc);
                ah[ma][1] = *(const uint32_t*)(sAh + (r0 + 8) * APAD + kc);
                ah[ma][2] = *(const uint32_t*)(sAh + r0 * APAD + kc + 8);
                ah[ma][3] = *(const uint32_t*)(sAh + (r0 + 8) * APAD + kc + 8);
                al[ma][0] = *(const uint32_t*)(sAl + r0 * APAD + kc);
                al[ma][1] = *(const uint32_t*)(sAl + (r0 + 8) * APAD + kc);
                al[ma][2] = *(const uint32_t*)(sAl + r0 * APAD + kc + 8);
                al[ma][3] = *(const uint32_t*)(sAl + (r0 + 8) * APAD + kc + 8);
            }
            #pragma unroll
            for (int na = 0; na < 4; na++) {
                int n0 = wn * 32 + na * 8 + g;
                uint32_t bh0 = *(const uint32_t*)(sBh + n0 * APAD + kc);
                uint32_t bh1 = *(const uint32_t*)(sBh + n0 * APAD + kc + 8);
                uint32_t bl0 = *(const uint32_t*)(sBl + n0 * APAD + kc);
                uint32_t bl1 = *(const uint32_t*)(sBl + n0 * APAD + kc + 8);
                #pragma unroll
                for (int ma = 0; ma < 2; ma++) {
                    mma_bf16(acc[ma][na], ah[ma][0], ah[ma][1], ah[ma][2], ah[ma][3], bh0, bh1);
                    mma_bf16(acc[ma][na], ah[ma][0], ah[ma][1], ah[ma][2], ah[ma][3], bl0, bl1);
                    mma_bf16(acc[ma][na], al[ma][0], al[ma][1], al[ma][2], al[ma][3], bh0, bh1);
                }
            }
        }
        __syncthreads();
    }

    // ---- epilogue ----
    #pragma unroll
    for (int ma = 0; ma < 2; ma++) {
        int row = rowBase + wm * 32 + ma * 16 + g;
        #pragma unroll
        for (int na = 0; na < 4; na++) {
            int col = colBase + wn * 32 + na * 8 + t * 2;
            if (row < M)
                *(float2*)(C + (size_t)row * Nc + col) = make_float2(acc[ma][na][0], acc[ma][na][1]);
            if (row + 8 < M)
                *(float2*)(C + (size_t)(row + 8) * Nc + col) = make_float2(acc[ma][na][2], acc[ma][na][3]);
        }
    }
}

// ================= graph kernels (unchanged, known-correct) =================
__global__ void attn_scores(const float* __restrict__ h, const float* __restrict__ asrc,
                            const float* __restrict__ adst, float* __restrict__ es,
                            float* __restrict__ ed, int N, int H, int C) {
    int wid = (blockIdx.x * blockDim.x + threadIdx.x) >> 5;
    int lane = threadIdx.x & 31;
    if (wid >= N * H) return;
    int n = wid / H, hh = wid - n * H;
    const float* hp = h + (size_t)n * H * C + (size_t)hh * C;
    float s1 = 0.f, s2 = 0.f;
    for (int c = lane; c < C; c += 32) {
        float v = hp[c];
        s1 += v * asrc[hh * C + c];
        s2 += v * adst[hh * C + c];
    }
    #pragma unroll
    for (int o = 16; o; o >>= 1) {
        s1 += __shfl_down_sync(0xffffffff, s1, o);
        s2 += __shfl_down_sync(0xffffffff, s2, o);
    }
    if (lane == 0) { es[wid] = s1; ed[wid] = s2; }
}

__global__ void edge_scores(int ET, int H) {
    int t = blockIdx.x * blockDim.x + threadIdx.x;
    if (t >= ET * H) return;
    int eid = t / H, hh = t - eid * H;
    float e = g_es[g_src[eid] * H + hh] + g_ed[g_dst[eid] * H + hh];
    e = e > 0.f ? e : 0.2f * e;
    float we = expf(e);
    g_w[t] = we;
    atomicAdd(&g_z[g_dst[eid] * H + hh], we);
}

__global__ void aggregate(const float* __restrict__ h, float* __restrict__ out,
                          int ET, int H, int C) {
    int wid = (blockIdx.x * blockDim.x + threadIdx.x) >> 5;
    int lane = threadIdx.x & 31;
    if (wid >= ET * H) return;
    int eid = wid / H, hh = wid - eid * H;
    int s = g_src[eid], d = g_dst[eid];
    float alpha = g_w[wid] / (g_z[d * H + hh] + 1e-16f);
    const float* hp = h + (size_t)s * H * C + (size_t)hh * C;
    float* op = out + (size_t)d * H * C + (size_t)hh * C;
    for (int c = lane; c < C; c += 32)
        atomicAdd(&op[c], alpha * hp[c]);
}

__global__ void bias_elu(float* __restrict__ x, const float* __restrict__ b,
                         int total, int HC) {
    int i = blockIdx.x * blockDim.x + threadIdx.x;
    if (i >= total) return;
    float v = x[i] + b[i % HC];
    x[i] = v > 0.f ? v : expm1f(v);
}

__global__ void risk_head(const float* __restrict__ h, const float* __restrict__ Wr,
                          const float* __restrict__ br, float* __restrict__ out, int N) {
    int wid = (blockIdx.x * blockDim.x + threadIdx.x) >> 5;
    int lane = threadIdx.x & 31;
    if (wid >= N) return;
    float s = 0.f;
    #pragma unroll
    for (int c = lane; c < 64; c += 32)
        s += h[(size_t)wid * 64 + c] * Wr[c];
    #pragma unroll
    for (int o = 16; o; o >>= 1)
        s += __shfl_down_sync(0xffffffff, s, o);
    if (lane == 0) out[wid] = 1.f / (1.f + expf(-(s + br[0])));
}

// ================= launch ====================================================
extern "C" void kernel_launch(void* const* d_in, const int* in_sizes, int n_in,
                              void* d_out, int out_size) {
    const float* x   = (const float*)d_in[0];
    const void*  ei  = d_in[1];
    const float* W1  = (const float*)d_in[2];
    const float* as1 = (const float*)d_in[3];
    const float* ad1 = (const float*)d_in[4];
    const float* b1  = (const float*)d_in[5];
    const float* W2  = (const float*)d_in[6];
    const float* as2 = (const float*)d_in[7];
    const float* ad2 = (const float*)d_in[8];
    const float* b2  = (const float*)d_in[9];
    const float* W3  = (const float*)d_in[10];
    const float* as3 = (const float*)d_in[11];
    const float* ad3 = (const float*)d_in[12];
    const float* b3  = (const float*)d_in[13];
    const float* Wr  = (const float*)d_in[14];
    const float* br  = (const float*)d_in[15];

    const int N  = in_sizes[0] / 66;
    const int E  = in_sizes[1] / 2;
    const int ET = E + N;

    cudaFuncSetAttribute(gemm_mma, cudaFuncAttributeMaxDynamicSharedMemorySize, SMEM_GEMM);

    void *p_h1, *p_a1, *p_h2, *p_a2, *p_h3, *p_a3, *p_z, *p_es, *p_ed, *p_wh, *p_wl;
    cudaGetSymbolAddress(&p_h1, g_h1);
    cudaGetSymbolAddress(&p_a1, g_a1);
    cudaGetSymbolAddress(&p_h2, g_h2);
    cudaGetSymbolAddress(&p_a2, g_a2);
    cudaGetSymbolAddress(&p_h3, g_h3);
    cudaGetSymbolAddress(&p_a3, g_a3);
    cudaGetSymbolAddress(&p_z,  g_z);
    cudaGetSymbolAddress(&p_es, g_es);
    cudaGetSymbolAddress(&p_ed, g_ed);
    cudaGetSymbolAddress(&p_wh, g_wth);
    cudaGetSymbolAddress(&p_wl, g_wtl);

    float* h1 = (float*)p_h1; float* a1 = (float*)p_a1;
    float* h2 = (float*)p_h2; float* a2 = (float*)p_a2;
    float* h3 = (float*)p_h3; float* a3 = (float*)p_a3;
    float* es = (float*)p_es; float* ed = (float*)p_ed;
    __nv_bfloat16* wh = (__nv_bfloat16*)p_wh;
    __nv_bfloat16* wl = (__nv_bfloat16*)p_wl;

    const int rowTiles = (N + 127) / 128;

    detect_dtype<<<1, 32>>>(ei, N);
    prep_edges<<<(ET + 255) / 256, 256>>>(ei, E, ET);

    // ---------------- layer 1: 66 -> 8x128 (Nc=1024, K=66, Kpad=128) --------
    cudaMemsetAsync(p_a1, 0, (size_t)N * 1024 * sizeof(float));
    cudaMemsetAsync(p_z,  0, (size_t)N * 8 * sizeof(float));
    prep_w<<<(1024 * 128 + 255) / 256, 256>>>(W1, wh, wl, 66, 1024, 128);
    {
        dim3 g(1024 / 64, rowTiles);
        gemm_mma<<<g, 256, SMEM_GEMM>>>(x, wh, wl, h1, N, 66, 128, 1024);
    }
    attn_scores<<<(N * 8 + 7) / 8, 256>>>(h1, as1, ad1, es, ed, N, 8, 128);
    edge_scores<<<(ET * 8 + 255) / 256, 256>>>(ET, 8);
    aggregate<<<(ET * 8 + 7) / 8, 256>>>(h1, a1, ET, 8, 128);
    bias_elu<<<((N * 1024) + 255) / 256, 256>>>(a1, b1, N * 1024, 1024);

    // ---------------- layer 2: 1024 -> 128 -----------------------------------
    cudaMemsetAsync(p_a2, 0, (size_t)N * 128 * sizeof(float));
    cudaMemsetAsync(p_z,  0, (size_t)N * 8 * sizeof(float));
    prep_w<<<(128 * 1024 + 255) / 256, 256>>>(W2, wh, wl, 1024, 128, 1024);
    {
        dim3 g(128 / 64, rowTiles);
        gemm_mma<<<g, 256, SMEM_GEMM>>>(a1, wh, wl, h2, N, 1024, 1024, 128);
    }
    attn_scores<<<(N + 7) / 8, 256>>>(h2, as2, ad2, es, ed, N, 1, 128);
    edge_scores<<<(ET + 255) / 256, 256>>>(ET, 1);
    aggregate<<<(ET + 7) / 8, 256>>>(h2, a2, ET, 1, 128);
    bias_elu<<<((N * 128) + 255) / 256, 256>>>(a2, b2, N * 128, 128);

    // ---------------- layer 3: 128 -> 64 --------------------------------------
    cudaMemsetAsync(p_a3, 0, (size_t)N * 64 * sizeof(float));
    cudaMemsetAsync(p_z,  0, (size_t)N * 8 * sizeof(float));
    prep_w<<<(64 * 128 + 255) / 256, 256>>>(W3, wh, wl, 128, 64, 128);
    {
        dim3 g(1, rowTiles);
        gemm_mma<<<g, 256, SMEM_GEMM>>>(a2, wh, wl, h3, N, 128, 128, 64);
    }
    attn_scores<<<(N + 7) / 8, 256>>>(h3, as3, ad3, es, ed, N, 1, 64);
    edge_scores<<<(ET + 255) / 256, 256>>>(ET, 1);
    aggregate<<<(ET + 7) / 8, 256>>>(h3, a3, ET, 1, 64);
    bias_elu<<<((N * 64) + 255) / 256, 256>>>(a3, b3, N * 64, 64);

    // ---------------- risk head ----------------------------------------------
    risk_head<<<(N + 7) / 8, 256>>>(a3, Wr, br, (float*)d_out, N);
}

// round 6
// speedup vs baseline: 1.8695x; 1.8695x over previous
#include <cuda_runtime.h>
#include <cuda_bf16.h>
#include <math.h>
#include <stdint.h>

#define NMAX 50000
#define EMAX 200000
#define ETMAX (NMAX + EMAX)

// ---------------- scratch (device globals; no allocations allowed) ----------
__device__ float g_h1[(size_t)NMAX * 1024];
__device__ float g_a1[(size_t)NMAX * 1024];
__device__ float g_h2[(size_t)NMAX * 128];
__device__ float g_a2[(size_t)NMAX * 128];
__device__ float g_h3[(size_t)NMAX * 64];
__device__ float g_a3[(size_t)NMAX * 64];
__device__ float g_es[(size_t)NMAX * 8];
__device__ float g_ed[(size_t)NMAX * 8];
__device__ float g_z [(size_t)NMAX * 8];
__device__ float g_w [(size_t)ETMAX * 8];
__device__ int   g_src[ETMAX];
__device__ int   g_dst[ETMAX];
__device__ int   g_is64;
// pre-split A operand (hi/lo bf16), [N][Kpad]
__device__ __nv_bfloat16 g_ah[(size_t)NMAX * 1024];
__device__ __nv_bfloat16 g_al[(size_t)NMAX * 1024];
// transposed + hi/lo-split weights, [Nc][Kpad] bf16 (reused across layers)
__device__ __nv_bfloat16 g_wth[131072];
__device__ __nv_bfloat16 g_wtl[131072];

// ================= edge preprocessing =======================================
__global__ void detect_dtype(const void* ei, int N) {
    if (blockIdx.x == 0 && threadIdx.x == 0) {
        const long long* p = (const long long*)ei;
        int ok = 1;
        for (int i = 0; i < 64; i++) {
            long long v = p[i];
            if (v < 0 || v >= (long long)N) { ok = 0; break; }
        }
        g_is64 = ok;
    }
}
__global__ void prep_edges(const void* ei, int E, int ET) {
    int i = blockIdx.x * blockDim.x + threadIdx.x;
    if (i >= ET) return;
    int s, d;
    if (i < E) {
        if (g_is64) { const long long* p = (const long long*)ei; s = (int)p[i]; d = (int)p[E + i]; }
        else        { const int* p = (const int*)ei; s = p[i]; d = p[E + i]; }
    } else { s = d = i - E; }
    g_src[i] = s; g_dst[i] = d;
}

// transpose + hi/lo split of W[K,N] into Wt[N,Kpad] bf16
__global__ void prep_w(const float* __restrict__ W, __nv_bfloat16* __restrict__ hi,
                       __nv_bfloat16* __restrict__ lo, int K, int N, int Kpad) {
    int idx = blockIdx.x * blockDim.x + threadIdx.x;
    if (idx >= N * Kpad) return;
    int n = idx / Kpad, k = idx - n * Kpad;
    float v = (k < K) ? W[(size_t)k * N + n] : 0.f;
    __nv_bfloat16 h = __float2bfloat16(v);
    hi[idx] = h;
    lo[idx] = __float2bfloat16(v - __bfloat162float(h));
}

// split x[N,K] -> hi/lo [N,Kpad] (zero-padded)
__global__ void split_x(const float* __restrict__ x, __nv_bfloat16* __restrict__ hi,
                        __nv_bfloat16* __restrict__ lo, int N, int K, int Kpad) {
    int idx = blockIdx.x * blockDim.x + threadIdx.x;
    if (idx >= N * Kpad) return;
    int n = idx / Kpad, k = idx - n * Kpad;
    float v = (k < K) ? x[(size_t)n * K + k] : 0.f;
    __nv_bfloat16 h = __float2bfloat16(v);
    hi[idx] = h;
    lo[idx] = __float2bfloat16(v - __bfloat162float(h));
}

// ================= mma.sync bf16-split GEMM ==================================
// C[M, Nc] = A[M, Kpad](split bf16) @ Wt^T   (Wt stored [Nc, Kpad] bf16 hi/lo)
// CTA tile 128x64, 8 warps of 32x32, K chunk 64. fp32 accum; 3-term split.
#define APAD 72     // smem row stride (elements) for A and B tiles
#define SMEM_GEMM ((128 * APAD * 2 + 64 * APAD * 2) * 2)   // 55296 bytes

__device__ __forceinline__ void mma_bf16(float* c, uint32_t a0, uint32_t a1,
                                         uint32_t a2, uint32_t a3,
                                         uint32_t b0, uint32_t b1) {
    asm volatile(
        "mma.sync.aligned.m16n8k16.row.col.f32.bf16.bf16.f32 "
        "{%0,%1,%2,%3}, {%4,%5,%6,%7}, {%8,%9}, {%0,%1,%2,%3};"
        : "+f"(c[0]), "+f"(c[1]), "+f"(c[2]), "+f"(c[3])
        : "r"(a0), "r"(a1), "r"(a2), "r"(a3), "r"(b0), "r"(b1));
}

__global__ void __launch_bounds__(256, 2)
gemm_mma(const __nv_bfloat16* __restrict__ Ah, const __nv_bfloat16* __restrict__ Al,
         const __nv_bfloat16* __restrict__ Bh, const __nv_bfloat16* __restrict__ Bl,
         float* __restrict__ C, int M, int Kpad, int Nc) {
    extern __shared__ __nv_bfloat16 sm[];
    __nv_bfloat16* sAh = sm;                 // [128][APAD]
    __nv_bfloat16* sAl = sAh + 128 * APAD;
    __nv_bfloat16* sBh = sAl + 128 * APAD;   // [64][APAD]
    __nv_bfloat16* sBl = sBh + 64 * APAD;

    const int tid = threadIdx.x;
    const int rowBase = blockIdx.y * 128, colBase = blockIdx.x * 64;
    const int warp = tid >> 5, lane = tid & 31;
    const int wm = warp & 3, wn = warp >> 2;      // 4x2 warp grid
    const int g = lane >> 2, t = lane & 3;

    float acc[2][4][4] = {};

    for (int k0 = 0; k0 < Kpad; k0 += 64) {
        // ---- A tile: 128 rows x 64 k (pre-split bf16), uint4 copies ----
        #pragma unroll
        for (int i = 0; i < 4; i++) {
            int lin = tid + (i << 8);
            int row = lin >> 3, u = lin & 7;
            int gr = rowBase + row;
            int e = row * APAD + (u << 3);
            uint4 hv = make_uint4(0, 0, 0, 0), lv = make_uint4(0, 0, 0, 0);
            if (gr < M) {
                size_t gidx = (size_t)gr * Kpad + k0 + (u << 3);
                hv = *(const uint4*)(Ah + gidx);
                lv = *(const uint4*)(Al + gidx);
            }
            *(uint4*)(sAh + e) = hv;
            *(uint4*)(sAl + e) = lv;
        }
        // ---- B tile: 64 n-rows x 64 k (pre-split bf16) ----
        #pragma unroll
        for (int i = 0; i < 2; i++) {
            int lin = tid + (i << 8);
            int n = lin >> 3, u = lin & 7;
            size_t gidx = (size_t)(colBase + n) * Kpad + k0 + (u << 3);
            int e = n * APAD + (u << 3);
            *(uint4*)(sBh + e) = *(const uint4*)(Bh + gidx);
            *(uint4*)(sBl + e) = *(const uint4*)(Bl + gidx);
        }
        __syncthreads();

        #pragma unroll
        for (int ks = 0; ks < 4; ks++) {
            const int kc = ks * 16 + t * 2;   // element col of this thread's k-pair
            uint32_t ah[2][4], al[2][4];
            #pragma unroll
            for (int ma = 0; ma < 2; ma++) {
                int r0 = wm * 32 + ma * 16 + g;
                ah[ma][0] = *(const uint32_t*)(sAh + r0 * APAD + kc);
                ah[ma][1] = *(const uint32_t*)(sAh + (r0 + 8) * APAD + kc);
                ah[ma][2] = *(const uint32_t*)(sAh + r0 * APAD + kc + 8);
                ah[ma][3] = *(const uint32_t*)(sAh + (r0 + 8) * APAD + kc + 8);
                al[ma][0] = *(const uint32_t*)(sAl + r0 * APAD + kc);
                al[ma][1] = *(const uint32_t*)(sAl + (r0 + 8) * APAD + kc);
                al[ma][2] = *(const uint32_t*)(sAl + r0 * APAD + kc + 8);
                al[ma][3] = *(const uint32_t*)(sAl + (r0 + 8) * APAD + kc + 8);
            }
            #pragma unroll
            for (int na = 0; na < 4; na++) {
                int n0 = wn * 32 + na * 8 + g;
                uint32_t bh0 = *(const uint32_t*)(sBh + n0 * APAD + kc);
                uint32_t bh1 = *(const uint32_t*)(sBh + n0 * APAD + kc + 8);
                uint32_t bl0 = *(const uint32_t*)(sBl + n0 * APAD + kc);
                uint32_t bl1 = *(const uint32_t*)(sBl + n0 * APAD + kc + 8);
                #pragma unroll
                for (int ma = 0; ma < 2; ma++) {
                    mma_bf16(acc[ma][na], ah[ma][0], ah[ma][1], ah[ma][2], ah[ma][3], bh0, bh1);
                    mma_bf16(acc[ma][na], ah[ma][0], ah[ma][1], ah[ma][2], ah[ma][3], bl0, bl1);
                    mma_bf16(acc[ma][na], al[ma][0], al[ma][1], al[ma][2], al[ma][3], bh0, bh1);
                }
            }
        }
        __syncthreads();
    }

    // ---- epilogue ----
    #pragma unroll
    for (int ma = 0; ma < 2; ma++) {
        int row = rowBase + wm * 32 + ma * 16 + g;
        #pragma unroll
        for (int na = 0; na < 4; na++) {
            int col = colBase + wn * 32 + na * 8 + t * 2;
            if (row < M)
                *(float2*)(C + (size_t)row * Nc + col) = make_float2(acc[ma][na][0], acc[ma][na][1]);
            if (row + 8 < M)
                *(float2*)(C + (size_t)(row + 8) * Nc + col) = make_float2(acc[ma][na][2], acc[ma][na][3]);
        }
    }
}

// ================= graph kernels =============================================
__global__ void attn_scores(const float* __restrict__ h, const float* __restrict__ asrc,
                            const float* __restrict__ adst, float* __restrict__ es,
                            float* __restrict__ ed, int N, int H, int C) {
    int wid = (blockIdx.x * blockDim.x + threadIdx.x) >> 5;
    int lane = threadIdx.x & 31;
    if (wid >= N * H) return;
    int n = wid / H, hh = wid - n * H;
    const float* hp = h + (size_t)n * H * C + (size_t)hh * C;
    float s1 = 0.f, s2 = 0.f;
    for (int c = lane; c < C; c += 32) {
        float v = hp[c];
        s1 += v * asrc[hh * C + c];
        s2 += v * adst[hh * C + c];
    }
    #pragma unroll
    for (int o = 16; o; o >>= 1) {
        s1 += __shfl_down_sync(0xffffffff, s1, o);
        s2 += __shfl_down_sync(0xffffffff, s2, o);
    }
    if (lane == 0) { es[wid] = s1; ed[wid] = s2; }
}

__global__ void edge_scores(int ET, int H) {
    int t = blockIdx.x * blockDim.x + threadIdx.x;
    if (t >= ET * H) return;
    int eid = t / H, hh = t - eid * H;
    float e = g_es[g_src[eid] * H + hh] + g_ed[g_dst[eid] * H + hh];
    e = e > 0.f ? e : 0.2f * e;
    float we = expf(e);
    g_w[t] = we;
    atomicAdd(&g_z[g_dst[eid] * H + hh], we);
}

__global__ void aggregate(const float* __restrict__ h, float* __restrict__ out,
                          int ET, int H, int C) {
    int wid = (blockIdx.x * blockDim.x + threadIdx.x) >> 5;
    int lane = threadIdx.x & 31;
    if (wid >= ET * H) return;
    int eid = wid / H, hh = wid - eid * H;
    int s = g_src[eid], d = g_dst[eid];
    float alpha = g_w[wid] / (g_z[d * H + hh] + 1e-16f);
    const float* hp = h + (size_t)s * H * C + (size_t)hh * C;
    float* op = out + (size_t)d * H * C + (size_t)hh * C;
    for (int c = lane; c < C; c += 32)
        atomicAdd(&op[c], alpha * hp[c]);
}

// bias + ELU, output written ONLY as split bf16 (next layer's A operand)
__global__ void bias_elu_split(const float* __restrict__ x, const float* __restrict__ b,
                               __nv_bfloat16* __restrict__ hi, __nv_bfloat16* __restrict__ lo,
                               int total, int HC) {
    int i = blockIdx.x * blockDim.x + threadIdx.x;
    if (i >= total) return;
    float v = x[i] + b[i % HC];
    v = v > 0.f ? v : expm1f(v);
    __nv_bfloat16 h = __float2bfloat16(v);
    hi[i] = h;
    lo[i] = __float2bfloat16(v - __bfloat162float(h));
}

__global__ void bias_elu(float* __restrict__ x, const float* __restrict__ b,
                         int total, int HC) {
    int i = blockIdx.x * blockDim.x + threadIdx.x;
    if (i >= total) return;
    float v = x[i] + b[i % HC];
    x[i] = v > 0.f ? v : expm1f(v);
}

__global__ void risk_head(const float* __restrict__ h, const float* __restrict__ Wr,
                          const float* __restrict__ br, float* __restrict__ out, int N) {
    int wid = (blockIdx.x * blockDim.x + threadIdx.x) >> 5;
    int lane = threadIdx.x & 31;
    if (wid >= N) return;
    float s = 0.f;
    #pragma unroll
    for (int c = lane; c < 64; c += 32)
        s += h[(size_t)wid * 64 + c] * Wr[c];
    #pragma unroll
    for (int o = 16; o; o >>= 1)
        s += __shfl_down_sync(0xffffffff, s, o);
    if (lane == 0) out[wid] = 1.f / (1.f + expf(-(s + br[0])));
}

// ================= launch ====================================================
extern "C" void kernel_launch(void* const* d_in, const int* in_sizes, int n_in,
                              void* d_out, int out_size) {
    const float* x   = (const float*)d_in[0];
    const void*  ei  = d_in[1];
    const float* W1  = (const float*)d_in[2];
    const float* as1 = (const float*)d_in[3];
    const float* ad1 = (const float*)d_in[4];
    const float* b1  = (const float*)d_in[5];
    const float* W2  = (const float*)d_in[6];
    const float* as2 = (const float*)d_in[7];
    const float* ad2 = (const float*)d_in[8];
    const float* b2  = (const float*)d_in[9];
    const float* W3  = (const float*)d_in[10];
    const float* as3 = (const float*)d_in[11];
    const float* ad3 = (const float*)d_in[12];
    const float* b3  = (const float*)d_in[13];
    const float* Wr  = (const float*)d_in[14];
    const float* br  = (const float*)d_in[15];

    const int N  = in_sizes[0] / 66;
    const int E  = in_sizes[1] / 2;
    const int ET = E + N;

    cudaFuncSetAttribute(gemm_mma, cudaFuncAttributeMaxDynamicSharedMemorySize, SMEM_GEMM);

    void *p_h1, *p_a1, *p_h2, *p_a2, *p_h3, *p_a3, *p_z, *p_es, *p_ed;
    void *p_wh, *p_wl, *p_ah, *p_al;
    cudaGetSymbolAddress(&p_h1, g_h1);
    cudaGetSymbolAddress(&p_a1, g_a1);
    cudaGetSymbolAddress(&p_h2, g_h2);
    cudaGetSymbolAddress(&p_a2, g_a2);
    cudaGetSymbolAddress(&p_h3, g_h3);
    cudaGetSymbolAddress(&p_a3, g_a3);
    cudaGetSymbolAddress(&p_z,  g_z);
    cudaGetSymbolAddress(&p_es, g_es);
    cudaGetSymbolAddress(&p_ed, g_ed);
    cudaGetSymbolAddress(&p_wh, g_wth);
    cudaGetSymbolAddress(&p_wl, g_wtl);
    cudaGetSymbolAddress(&p_ah, g_ah);
    cudaGetSymbolAddress(&p_al, g_al);

    float* h1 = (float*)p_h1; float* a1 = (float*)p_a1;
    float* h2 = (float*)p_h2; float* a2 = (float*)p_a2;
    float* h3 = (float*)p_h3; float* a3 = (float*)p_a3;
    float* es = (float*)p_es; float* ed = (float*)p_ed;
    __nv_bfloat16* wh = (__nv_bfloat16*)p_wh;
    __nv_bfloat16* wl = (__nv_bfloat16*)p_wl;
    __nv_bfloat16* ah = (__nv_bfloat16*)p_ah;
    __nv_bfloat16* al = (__nv_bfloat16*)p_al;

    const int rowTiles = (N + 127) / 128;

    detect_dtype<<<1, 32>>>(ei, N);
    prep_edges<<<(ET + 255) / 256, 256>>>(ei, E, ET);

    // ---------------- layer 1: 66 -> 8x128 (Nc=1024, Kpad=128) --------------
    cudaMemsetAsync(p_a1, 0, (size_t)N * 1024 * sizeof(float));
    cudaMemsetAsync(p_z,  0, (size_t)N * 8 * sizeof(float));
    split_x<<<((N * 128) + 255) / 256, 256>>>(x, ah, al, N, 66, 128);
    prep_w<<<(1024 * 128 + 255) / 256, 256>>>(W1, wh, wl, 66, 1024, 128);
    {
        dim3 g(1024 / 64, rowTiles);
        gemm_mma<<<g, 256, SMEM_GEMM>>>(ah, al, wh, wl, h1, N, 128, 1024);
    }
    attn_scores<<<(N * 8 + 7) / 8, 256>>>(h1, as1, ad1, es, ed, N, 8, 128);
    edge_scores<<<(ET * 8 + 255) / 256, 256>>>(ET, 8);
    aggregate<<<(ET * 8 + 7) / 8, 256>>>(h1, a1, ET, 8, 128);
    bias_elu_split<<<((N * 1024) + 255) / 256, 256>>>(a1, b1, ah, al, N * 1024, 1024);

    // ---------------- layer 2: 1024 -> 128 (Nc=128, Kpad=1024) ---------------
    cudaMemsetAsync(p_a2, 0, (size_t)N * 128 * sizeof(float));
    cudaMemsetAsync(p_z,  0, (size_t)N * 8 * sizeof(float));
    prep_w<<<(128 * 1024 + 255) / 256, 256>>>(W2, wh, wl, 1024, 128, 1024);
    {
        dim3 g(128 / 64, rowTiles);
        gemm_mma<<<g, 256, SMEM_GEMM>>>(ah, al, wh, wl, h2, N, 1024, 128);
    }
    attn_scores<<<(N + 7) / 8, 256>>>(h2, as2, ad2, es, ed, N, 1, 128);
    edge_scores<<<(ET + 255) / 256, 256>>>(ET, 1);
    aggregate<<<(ET + 7) / 8, 256>>>(h2, a2, ET, 1, 128);
    bias_elu_split<<<((N * 128) + 255) / 256, 256>>>(a2, b2, ah, al, N * 128, 128);

    // ---------------- layer 3: 128 -> 64 (Nc=64, Kpad=128) -------------------
    cudaMemsetAsync(p_a3, 0, (size_t)N * 64 * sizeof(float));
    cudaMemsetAsync(p_z,  0, (size_t)N * 8 * sizeof(float));
    prep_w<<<(64 * 128 + 255) / 256, 256>>>(W3, wh, wl, 128, 64, 128);
    {
        dim3 g(1, rowTiles);
        gemm_mma<<<g, 256, SMEM_GEMM>>>(ah, al, wh, wl, h3, N, 128, 64);
    }
    attn_scores<<<(N + 7) / 8, 256>>>(h3, as3, ad3, es, ed, N, 1, 64);
    edge_scores<<<(ET + 255) / 256, 256>>>(ET, 1);
    aggregate<<<(ET + 7) / 8, 256>>>(h3, a3, ET, 1, 64);
    bias_elu<<<((N * 64) + 255) / 256, 256>>>(a3, b3, N * 64, 64);

    // ---------------- risk head ----------------------------------------------
    risk_head<<<(N + 7) / 8, 256>>>(a3, Wr, br, (float*)d_out, N);
}

// round 8
// speedup vs baseline: 2.9990x; 1.6042x over previous
#include <cuda_runtime.h>
#include <cuda_bf16.h>
#include <math.h>
#include <stdint.h>

#define NMAX 50000
#define EMAX 200000
#define ETMAX (NMAX + EMAX)

// ---------------- scratch (device globals; no allocations allowed) ----------
__device__ float g_h1[(size_t)NMAX * 1024];   // GEMM outputs (h), reused per layer
__device__ float g_es[(size_t)NMAX * 8];
__device__ float g_ed[(size_t)NMAX * 8];
__device__ float g_w [(size_t)ETMAX * 8];
__device__ int   g_src[ETMAX];
__device__ int   g_dst[ETMAX];
__device__ int   g_is64;
// CSR by dst
__device__ int   g_cnt[NMAX];
__device__ int   g_roff[NMAX + 1];
__device__ int   g_pos[NMAX];
__device__ int   g_bsum[64];
__device__ int   g_eid[ETMAX];
// pre-split A operand (hi/lo bf16), [N][Kpad]
__device__ __nv_bfloat16 g_ah[(size_t)NMAX * 1024];
__device__ __nv_bfloat16 g_al[(size_t)NMAX * 1024];
// transposed + hi/lo-split weights, [Nc][Kpad] bf16
__device__ __nv_bfloat16 g_wth[131072];
__device__ __nv_bfloat16 g_wtl[131072];

// ================= edge preprocessing =======================================
__global__ void detect_dtype(const void* ei, int N) {
    if (blockIdx.x == 0 && threadIdx.x == 0) {
        const long long* p = (const long long*)ei;
        int ok = 1;
        for (int i = 0; i < 64; i++) {
            long long v = p[i];
            if (v < 0 || v >= (long long)N) { ok = 0; break; }
        }
        g_is64 = ok;
    }
}
__global__ void prep_edges(const void* ei, int E, int ET) {
    int i = blockIdx.x * blockDim.x + threadIdx.x;
    if (i >= ET) return;
    int s, d;
    if (i < E) {
        if (g_is64) { const long long* p = (const long long*)ei; s = (int)p[i]; d = (int)p[E + i]; }
        else        { const int* p = (const int*)ei; s = p[i]; d = p[E + i]; }
    } else { s = d = i - E; }
    g_src[i] = s; g_dst[i] = d;
}

// ---------------- CSR build --------------------------------------------------
__global__ void csr_hist(int ET) {
    int i = blockIdx.x * blockDim.x + threadIdx.x;
    if (i < ET) atomicAdd(&g_cnt[g_dst[i]], 1);
}
#define SCAN_B 1024
__global__ void scan1(int n) {
    __shared__ int sh[SCAN_B];
    int gid = blockIdx.x * SCAN_B + threadIdx.x;
    int v = (gid < n) ? g_cnt[gid] : 0;
    sh[threadIdx.x] = v;
    __syncthreads();
    for (int o = 1; o < SCAN_B; o <<= 1) {
        int t = (threadIdx.x >= o) ? sh[threadIdx.x - o] : 0;
        __syncthreads();
        sh[threadIdx.x] += t;
        __syncthreads();
    }
    if (gid < n) g_roff[gid] = sh[threadIdx.x] - v;   // exclusive
    if (threadIdx.x == SCAN_B - 1) g_bsum[blockIdx.x] = sh[threadIdx.x];
}
__global__ void scan2(int nb) {
    __shared__ int sh[64];
    int v = (threadIdx.x < nb) ? g_bsum[threadIdx.x] : 0;
    sh[threadIdx.x] = v;
    __syncthreads();
    for (int o = 1; o < 64; o <<= 1) {
        int t = (threadIdx.x >= o) ? sh[threadIdx.x - o] : 0;
        __syncthreads();
        sh[threadIdx.x] += t;
        __syncthreads();
    }
    if (threadIdx.x < nb) g_bsum[threadIdx.x] = sh[threadIdx.x] - v;
}
__global__ void scan3(int n, int ET) {
    int gid = blockIdx.x * SCAN_B + threadIdx.x;
    if (gid < n) {
        int v = g_roff[gid] + g_bsum[blockIdx.x];
        g_roff[gid] = v;
        g_pos[gid] = v;
    }
    if (gid == 0) g_roff[n] = ET;
}
__global__ void csr_fill(int ET) {
    int i = blockIdx.x * blockDim.x + threadIdx.x;
    if (i >= ET) return;
    int slot = atomicAdd(&g_pos[g_dst[i]], 1);
    g_eid[slot] = i;
}

// ---------------- weight / input prep ---------------------------------------
__global__ void prep_w(const float* __restrict__ W, __nv_bfloat16* __restrict__ hi,
                       __nv_bfloat16* __restrict__ lo, int K, int N, int Kpad) {
    int idx = blockIdx.x * blockDim.x + threadIdx.x;
    if (idx >= N * Kpad) return;
    int n = idx / Kpad, k = idx - n * Kpad;
    float v = (k < K) ? W[(size_t)k * N + n] : 0.f;
    __nv_bfloat16 h = __float2bfloat16(v);
    hi[idx] = h;
    lo[idx] = __float2bfloat16(v - __bfloat162float(h));
}
__global__ void split_x(const float* __restrict__ x, __nv_bfloat16* __restrict__ hi,
                        __nv_bfloat16* __restrict__ lo, int N, int K, int Kpad) {
    int idx = blockIdx.x * blockDim.x + threadIdx.x;
    if (idx >= N * Kpad) return;
    int n = idx / Kpad, k = idx - n * Kpad;
    float v = (k < K) ? x[(size_t)n * K + k] : 0.f;
    __nv_bfloat16 h = __float2bfloat16(v);
    hi[idx] = h;
    lo[idx] = __float2bfloat16(v - __bfloat162float(h));
}

// ================= mma.sync bf16-split GEMM + fused attn-dot epilogue =======
#define APAD 72
#define SMEM_GEMM ((128 * APAD * 2 + 64 * APAD * 2) * 2)   // 55296 bytes

__device__ __forceinline__ void mma_bf16(float* c, uint32_t a0, uint32_t a1,
                                         uint32_t a2, uint32_t a3,
                                         uint32_t b0, uint32_t b1) {
    asm volatile(
        "mma.sync.aligned.m16n8k16.row.col.f32.bf16.bf16.f32 "
        "{%0,%1,%2,%3}, {%4,%5,%6,%7}, {%8,%9}, {%0,%1,%2,%3};"
        : "+f"(c[0]), "+f"(c[1]), "+f"(c[2]), "+f"(c[3])
        : "r"(a0), "r"(a1), "r"(a2), "r"(a3), "r"(b0), "r"(b1));
}

__global__ void __launch_bounds__(256, 2)
gemm_mma(const __nv_bfloat16* __restrict__ Ah, const __nv_bfloat16* __restrict__ Al,
         const __nv_bfloat16* __restrict__ Bh, const __nv_bfloat16* __restrict__ Bl,
         float* __restrict__ C, int M, int Kpad, int Nc,
         const float* __restrict__ av, const float* __restrict__ adv,
         float* __restrict__ esOut, float* __restrict__ edOut, int H, int Ch) {
    extern __shared__ __nv_bfloat16 sm[];
    __nv_bfloat16* sAh = sm;
    __nv_bfloat16* sAl = sAh + 128 * APAD;
    __nv_bfloat16* sBh = sAl + 128 * APAD;
    __nv_bfloat16* sBl = sBh + 64 * APAD;

    const int tid = threadIdx.x;
    const int rowBase = blockIdx.y * 128, colBase = blockIdx.x * 64;
    const int warp = tid >> 5, lane = tid & 31;
    const int wm = warp & 3, wn = warp >> 2;
    const int g = lane >> 2, t = lane & 3;

    float acc[2][4][4] = {};

    for (int k0 = 0; k0 < Kpad; k0 += 64) {
        #pragma unroll
        for (int i = 0; i < 4; i++) {
            int lin = tid + (i << 8);
            int row = lin >> 3, u = lin & 7;
            int gr = rowBase + row;
            int e = row * APAD + (u << 3);
            uint4 hv = make_uint4(0, 0, 0, 0), lv = make_uint4(0, 0, 0, 0);
            if (gr < M) {
                size_t gidx = (size_t)gr * Kpad + k0 + (u << 3);
                hv = *(const uint4*)(Ah + gidx);
                lv = *(const uint4*)(Al + gidx);
            }
            *(uint4*)(sAh + e) = hv;
            *(uint4*)(sAl + e) = lv;
        }
        #pragma unroll
        for (int i = 0; i < 2; i++) {
            int lin = tid + (i << 8);
            int n = lin >> 3, u = lin & 7;
            size_t gidx = (size_t)(colBase + n) * Kpad + k0 + (u << 3);
            int e = n * APAD + (u << 3);
            *(uint4*)(sBh + e) = *(const uint4*)(Bh + gidx);
            *(uint4*)(sBl + e) = *(const uint4*)(Bl + gidx);
        }
        __syncthreads();

        #pragma unroll
        for (int ks = 0; ks < 4; ks++) {
            const int kc = ks * 16 + t * 2;
            uint32_t ah[2][4], al[2][4];
            #pragma unroll
            for (int ma = 0; ma < 2; ma++) {
                int r0 = wm * 32 + ma * 16 + g;
                ah[ma][0] = *(const uint32_t*)(sAh + r0 * APAD + kc);
                ah[ma][1] = *(const uint32_t*)(sAh + (r0 + 8) * APAD + kc);
                ah[ma][2] = *(const uint32_t*)(sAh + r0 * APAD + kc + 8);
                ah[ma][3] = *(const uint32_t*)(sAh + (r0 + 8) * APAD + kc + 8);
                al[ma][0] = *(const uint32_t*)(sAl + r0 * APAD + kc);
                al[ma][1] = *(const uint32_t*)(sAl + (r0 + 8) * APAD + kc);
                al[ma][2] = *(const uint32_t*)(sAl + r0 * APAD + kc + 8);
                al[ma][3] = *(const uint32_t*)(sAl + (r0 + 8) * APAD + kc + 8);
            }
            #pragma unroll
            for (int na = 0; na < 4; na++) {
                int n0 = wn * 32 + na * 8 + g;
                uint32_t bh0 = *(const uint32_t*)(sBh + n0 * APAD + kc);
                uint32_t bh1 = *(const uint32_t*)(sBh + n0 * APAD + kc + 8);
                uint32_t bl0 = *(const uint32_t*)(sBl + n0 * APAD + kc);
                uint32_t bl1 = *(const uint32_t*)(sBl + n0 * APAD + kc + 8);
                #pragma unroll
                for (int ma = 0; ma < 2; ma++) {
                    mma_bf16(acc[ma][na], ah[ma][0], ah[ma][1], ah[ma][2], ah[ma][3], bh0, bh1);
                    mma_bf16(acc[ma][na], ah[ma][0], ah[ma][1], ah[ma][2], ah[ma][3], bl0, bl1);
                    mma_bf16(acc[ma][na], al[ma][0], al[ma][1], al[ma][2], al[ma][3], bh0, bh1);
                }
            }
        }
        __syncthreads();
    }

    // ---- store C ----
    #pragma unroll
    for (int ma = 0; ma < 2; ma++) {
        int row = rowBase + wm * 32 + ma * 16 + g;
        #pragma unroll
        for (int na = 0; na < 4; na++) {
            int col = colBase + wn * 32 + na * 8 + t * 2;
            if (row < M)
                *(float2*)(C + (size_t)row * Nc + col) = make_float2(acc[ma][na][0], acc[ma][na][1]);
            if (row + 8 < M)
                *(float2*)(C + (size_t)(row + 8) * Nc + col) = make_float2(acc[ma][na][2], acc[ma][na][3]);
        }
    }

    // ---- fused attention dots: es/ed partial sums (tile cols lie in ONE head) ----
    {
        const int head = colBase / Ch;                 // Ch in {64,128}, tile=64
        const int cb = colBase - head * Ch;            // col offset within head
        const float* avh = av + head * Ch + cb;
        const float* adh = adv + head * Ch + cb;
        #pragma unroll
        for (int ma = 0; ma < 2; ma++) {
            float pe0 = 0.f, pd0 = 0.f, pe1 = 0.f, pd1 = 0.f;
            #pragma unroll
            for (int na = 0; na < 4; na++) {
                int cl = wn * 32 + na * 8 + t * 2;
                float w0 = avh[cl], w1 = avh[cl + 1];
                float d0 = adh[cl], d1 = adh[cl + 1];
                pe0 += acc[ma][na][0] * w0 + acc[ma][na][1] * w1;
                pd0 += acc[ma][na][0] * d0 + acc[ma][na][1] * d1;
                pe1 += acc[ma][na][2] * w0 + acc[ma][na][3] * w1;
                pd1 += acc[ma][na][2] * d0 + acc[ma][na][3] * d1;
            }
            // reduce over the 4 t-lanes of this row group
            #pragma unroll
            for (int o = 1; o <= 2; o <<= 1) {
                pe0 += __shfl_xor_sync(0xffffffff, pe0, o);
                pd0 += __shfl_xor_sync(0xffffffff, pd0, o);
                pe1 += __shfl_xor_sync(0xffffffff, pe1, o);
                pd1 += __shfl_xor_sync(0xffffffff, pd1, o);
            }
            if (t == 0) {
                int r = rowBase + wm * 32 + ma * 16 + g;
                if (r < M) {
                    atomicAdd(&esOut[(size_t)r * H + head], pe0);
                    atomicAdd(&edOut[(size_t)r * H + head], pd0);
                }
                if (r + 8 < M) {
                    atomicAdd(&esOut[(size_t)(r + 8) * H + head], pe1);
                    atomicAdd(&edOut[(size_t)(r + 8) * H + head], pd1);
                }
            }
        }
    }
}

// ================= graph kernels =============================================
// edge weights, no atomics (denominator handled in the CSR aggregate)
__global__ void edge_w(int ET, int H) {
    int tdx = blockIdx.x * blockDim.x + threadIdx.x;
    if (tdx >= ET * H) return;
    int eid = tdx / H, hh = tdx - eid * H;
    float e = g_es[(size_t)g_src[eid] * H + hh] + g_ed[(size_t)g_dst[eid] * H + hh];
    e = e > 0.f ? e : 0.2f * e;
    g_w[tdx] = expf(e);
}

// CSR aggregate + bias + ELU + bf16 hi/lo split (layers 1-2)
__global__ void agg_split(const float* __restrict__ h, const float* __restrict__ b,
                          __nv_bfloat16* __restrict__ hi, __nv_bfloat16* __restrict__ lo,
                          int N, int H, int C) {
    int wid = (blockIdx.x * blockDim.x + threadIdx.x) >> 5;
    int lane = threadIdx.x & 31;
    if (wid >= N * H) return;
    int d = wid / H, hh = wid - d * H;
    int e0 = g_roff[d], e1 = g_roff[d + 1];

    float z = 0.f;
    for (int e = e0 + lane; e < e1; e += 32) z += g_w[(size_t)g_eid[e] * H + hh];
    #pragma unroll
    for (int o = 16; o; o >>= 1) z += __shfl_xor_sync(0xffffffff, z, o);
    float invz = 1.f / (z + 1e-16f);

    float acc[4] = {0.f, 0.f, 0.f, 0.f};
    const int nj = C >> 5;
    for (int e = e0; e < e1; e++) {
        int id = g_eid[e];
        float alpha = g_w[(size_t)id * H + hh] * invz;
        const float* hp = h + (size_t)g_src[id] * H * C + (size_t)hh * C;
        #pragma unroll
        for (int j = 0; j < 4; j++)
            if (j < nj) acc[j] += alpha * hp[lane + 32 * j];
    }
    size_t obase = (size_t)d * H * C + (size_t)hh * C;
    #pragma unroll
    for (int j = 0; j < 4; j++) {
        if (j >= nj) break;
        int c = lane + 32 * j;
        float v = acc[j] + b[hh * C + c];
        v = v > 0.f ? v : expm1f(v);
        __nv_bfloat16 hv = __float2bfloat16(v);
        hi[obase + c] = hv;
        lo[obase + c] = __float2bfloat16(v - __bfloat162float(hv));
    }
}

// CSR aggregate + bias + ELU + risk head (layer 3, H=1, C=64) -> d_out
__global__ void agg_risk(const float* __restrict__ h, const float* __restrict__ b,
                         const float* __restrict__ Wr, const float* __restrict__ br,
                         float* __restrict__ out, int N) {
    int wid = (blockIdx.x * blockDim.x + threadIdx.x) >> 5;
    int lane = threadIdx.x & 31;
    if (wid >= N) return;
    int d = wid;
    int e0 = g_roff[d], e1 = g_roff[d + 1];

    float z = 0.f;
    for (int e = e0 + lane; e < e1; e += 32) z += g_w[g_eid[e]];
    #pragma unroll
    for (int o = 16; o; o >>= 1) z += __shfl_xor_sync(0xffffffff, z, o);
    float invz = 1.f / (z + 1e-16f);

    float a0 = 0.f, a1 = 0.f;
    for (int e = e0; e < e1; e++) {
        int id = g_eid[e];
        float alpha = g_w[id] * invz;
        const float* hp = h + (size_t)g_src[id] * 64;
        a0 += alpha * hp[lane];
        a1 += alpha * hp[lane + 32];
    }
    float v0 = a0 + b[lane];        v0 = v0 > 0.f ? v0 : expm1f(v0);
    float v1 = a1 + b[lane + 32];   v1 = v1 > 0.f ? v1 : expm1f(v1);
    float s = v0 * Wr[lane] + v1 * Wr[lane + 32];
    #pragma unroll
    for (int o = 16; o; o >>= 1) s += __shfl_xor_sync(0xffffffff, s, o);
    if (lane == 0) out[d] = 1.f / (1.f + expf(-(s + br[0])));
}

// ================= launch ====================================================
extern "C" void kernel_launch(void* const* d_in, const int* in_sizes, int n_in,
                              void* d_out, int out_size) {
    const float* x   = (const float*)d_in[0];
    const void*  ei  = d_in[1];
    const float* W1  = (const float*)d_in[2];
    const float* as1 = (const float*)d_in[3];
    const float* ad1 = (const float*)d_in[4];
    const float* b1  = (const float*)d_in[5];
    const float* W2  = (const float*)d_in[6];
    const float* as2 = (const float*)d_in[7];
    const float* ad2 = (const float*)d_in[8];
    const float* b2  = (const float*)d_in[9];
    const float* W3  = (const float*)d_in[10];
    const float* as3 = (const float*)d_in[11];
    const float* ad3 = (const float*)d_in[12];
    const float* b3  = (const float*)d_in[13];
    const float* Wr  = (const float*)d_in[14];
    const float* br  = (const float*)d_in[15];

    const int N  = in_sizes[0] / 66;
    const int E  = in_sizes[1] / 2;
    const int ET = E + N;
    const int nb = (N + SCAN_B - 1) / SCAN_B;

    cudaFuncSetAttribute(gemm_mma, cudaFuncAttributeMaxDynamicSharedMemorySize, SMEM_GEMM);

    void *p_h, *p_es, *p_ed, *p_wh, *p_wl, *p_ah, *p_al, *p_cnt;
    cudaGetSymbolAddress(&p_h,  g_h1);
    cudaGetSymbolAddress(&p_es, g_es);
    cudaGetSymbolAddress(&p_ed, g_ed);
    cudaGetSymbolAddress(&p_wh, g_wth);
    cudaGetSymbolAddress(&p_wl, g_wtl);
    cudaGetSymbolAddress(&p_ah, g_ah);
    cudaGetSymbolAddress(&p_al, g_al);
    cudaGetSymbolAddress(&p_cnt, g_cnt);

    float* h  = (float*)p_h;
    float* es = (float*)p_es; float* ed = (float*)p_ed;
    __nv_bfloat16* wh = (__nv_bfloat16*)p_wh;
    __nv_bfloat16* wl = (__nv_bfloat16*)p_wl;
    __nv_bfloat16* ah = (__nv_bfloat16*)p_ah;
    __nv_bfloat16* al = (__nv_bfloat16*)p_al;

    const int rowTiles = (N + 127) / 128;

    // ---- edges + CSR (built once) ----
    detect_dtype<<<1, 32>>>(ei, N);
    prep_edges<<<(ET + 255) / 256, 256>>>(ei, E, ET);
    cudaMemsetAsync(p_cnt, 0, N * sizeof(int));
    csr_hist<<<(ET + 255) / 256, 256>>>(ET);
    scan1<<<nb, SCAN_B>>>(N);
    scan2<<<1, 64>>>(nb);
    scan3<<<nb, SCAN_B>>>(N, ET);
    csr_fill<<<(ET + 255) / 256, 256>>>(ET);

    // ---------------- layer 1: 66 -> 8x128 (Nc=1024, Kpad=128, H=8, C=128) --
    cudaMemsetAsync(p_es, 0, (size_t)N * 8 * sizeof(float));
    cudaMemsetAsync(p_ed, 0, (size_t)N * 8 * sizeof(float));
    split_x<<<((N * 128) + 255) / 256, 256>>>(x, ah, al, N, 66, 128);
    prep_w<<<(1024 * 128 + 255) / 256, 256>>>(W1, wh, wl, 66, 1024, 128);
    {
        dim3 g(1024 / 64, rowTiles);
        gemm_mma<<<g, 256, SMEM_GEMM>>>(ah, al, wh, wl, h, N, 128, 1024,
                                        as1, ad1, es, ed, 8, 128);
    }
    edge_w<<<(ET * 8 + 255) / 256, 256>>>(ET, 8);
    agg_split<<<(N * 8 + 7) / 8, 256>>>(h, b1, ah, al, N, 8, 128);

    // ---------------- layer 2: 1024 -> 128 (Nc=128, Kpad=1024, H=1, C=128) ---
    cudaMemsetAsync(p_es, 0, (size_t)N * sizeof(float));
    cudaMemsetAsync(p_ed, 0, (size_t)N * sizeof(float));
    prep_w<<<(128 * 1024 + 255) / 256, 256>>>(W2, wh, wl, 1024, 128, 1024);
    {
        dim3 g(128 / 64, rowTiles);
        gemm_mma<<<g, 256, SMEM_GEMM>>>(ah, al, wh, wl, h, N, 1024, 128,
                                        as2, ad2, es, ed, 1, 128);
    }
    edge_w<<<(ET + 255) / 256, 256>>>(ET, 1);
    agg_split<<<(N + 7) / 8, 256>>>(h, b2, ah, al, N, 1, 128);

    // ---------------- layer 3: 128 -> 64 (Nc=64, Kpad=128, H=1, C=64) --------
    cudaMemsetAsync(p_es, 0, (size_t)N * sizeof(float));
    cudaMemsetAsync(p_ed, 0, (size_t)N * sizeof(float));
    prep_w<<<(64 * 128 + 255) / 256, 256>>>(W3, wh, wl, 128, 64, 128);
    {
        dim3 g(1, rowTiles);
        gemm_mma<<<g, 256, SMEM_GEMM>>>(ah, al, wh, wl, h, N, 128, 64,
                                        as3, ad3, es, ed, 1, 64);
    }
    edge_w<<<(ET + 255) / 256, 256>>>(ET, 1);
    agg_risk<<<(N + 7) / 8, 256>>>(h, b3, Wr, br, (float*)d_out, N);
}